// round 7
// baseline (speedup 1.0000x reference)
#include <cuda_runtime.h>
#include <cuda_bf16.h>
#include <cstdint>

#define H 128
#define BM 128
#define MAXN 50176
#define MAXE 800000

// ---------------- scratch (device globals) ----------------
__device__ float g_P[MAXN * H];
__device__ float g_Q[MAXN * H];
__device__ float g_Hsum[MAXN * H];
__device__ float g_agg[MAXN * H];
__device__ float g_Tbuf[MAXN * H];
__device__ int   g_cnt[MAXN];        // in-degree histogram
__device__ int   g_scan[MAXN];       // per-block exclusive scan
__device__ int   g_bsum[256];        // block sums
__device__ int   g_start[MAXN];      // atomic cursors for counting sort
__device__ int   g_row[MAXE];
__device__ int   g_col[MAXE];
__device__ int   g_sorted[MAXE];     // edge ids sorted by col
__device__ int   g_not64;
// 7 weight tiles x (hi,lo): B^T[n][k] bf16, packed 256B rows, 32KB each
__device__ __align__(16) char g_Wimg[14 * 32768];

// ---------------- smem layout ----------------
#define TSTRIDE 272
#define TILE    (128 * TSTRIDE)          // 34816
#define SM_AH   0
#define SM_AL   TILE
#define SM_WH   (2 * TILE)               // 69632 (h-tile overlays here post-GEMM)
#define SM_WL   (3 * TILE)
#define SM_HT   (2 * TILE)               // 128 x 528B = 67584, fits in W region
#define HTSTRIDE 528
#define SM_EID  (4 * TILE)               // 139264
#define SM_RID  (4 * TILE + 512)
#define SM_CID  (4 * TILE + 1024)
#define SMEM_NODE (4 * TILE)
#define SMEM_EDGE (4 * TILE + 1536)

// ---------------- PTX helpers ----------------
__device__ __forceinline__ uint32_t smem_u32(const void* p) {
    uint32_t a;
    asm("{ .reg .u64 t; cvta.to.shared.u64 t, %1; cvt.u32.u64 %0, t; }" : "=r"(a) : "l"(p));
    return a;
}
__device__ __forceinline__ void ldsm_x4(uint32_t* r, uint32_t addr) {
    asm volatile("ldmatrix.sync.aligned.m8n8.x4.shared.b16 {%0,%1,%2,%3}, [%4];"
                 : "=r"(r[0]), "=r"(r[1]), "=r"(r[2]), "=r"(r[3]) : "r"(addr));
}
__device__ __forceinline__ void mma16816(float* d, const uint32_t* a, uint32_t b0, uint32_t b1) {
    asm volatile("mma.sync.aligned.m16n8k16.row.col.f32.bf16.bf16.f32 "
                 "{%0,%1,%2,%3}, {%4,%5,%6,%7}, {%8,%9}, {%0,%1,%2,%3};"
                 : "+f"(d[0]), "+f"(d[1]), "+f"(d[2]), "+f"(d[3])
                 : "r"(a[0]), "r"(a[1]), "r"(a[2]), "r"(a[3]), "r"(b0), "r"(b1));
}
__device__ __forceinline__ void red_add_v4(float* p, float4 v) {
    asm volatile("red.global.add.v4.f32 [%0], {%1,%2,%3,%4};"
                 :: "l"(p), "f"(v.x), "f"(v.y), "f"(v.z), "f"(v.w) : "memory");
}

__device__ __forceinline__ void split2(float a, float b, uint32_t& hi, uint32_t& lo) {
    __nv_bfloat16 ha = __float2bfloat16_rn(a), hb = __float2bfloat16_rn(b);
    float ra = a - __bfloat162float(ha), rb = b - __bfloat162float(hb);
    __nv_bfloat16 la = __float2bfloat16_rn(ra), lb = __float2bfloat16_rn(rb);
    hi = ((uint32_t)*(uint16_t*)&hb << 16) | (uint32_t)*(uint16_t*)&ha;
    lo = ((uint32_t)*(uint16_t*)&lb << 16) | (uint32_t)*(uint16_t*)&la;
}

// load fp32 A tile (contiguous rows), split to bf16 hi/lo smem tiles
__device__ __forceinline__ void load_convert_A(const float* __restrict__ A, int gm, int M,
                                               char* sm, int tid) {
#pragma unroll
    for (int it = 0; it < 16; ++it) {
        int idx = tid + it * 256;
        int m = idx >> 5;
        int k4 = (idx & 31) << 2;
        float4 v = make_float4(0.f, 0.f, 0.f, 0.f);
        int gr = gm + m;
        if (gr < M) v = *(const float4*)(A + (size_t)gr * H + k4);
        uint32_t h0, l0, h1, l1;
        split2(v.x, v.y, h0, l0);
        split2(v.z, v.w, h1, l1);
        uint32_t off = (uint32_t)m * TSTRIDE + (uint32_t)k4 * 2;
        *(uint2*)(sm + SM_AH + off) = make_uint2(h0, h1);
        *(uint2*)(sm + SM_AL + off) = make_uint2(l0, l1);
    }
}

// gathered variant: row m comes from A[eid[m]]
__device__ __forceinline__ void load_convert_A_gather(const float* __restrict__ A,
                                                      const int* __restrict__ eid,
                                                      char* sm, int tid) {
#pragma unroll
    for (int it = 0; it < 16; ++it) {
        int idx = tid + it * 256;
        int m = idx >> 5;
        int k4 = (idx & 31) << 2;
        int e = eid[m];
        float4 v = make_float4(0.f, 0.f, 0.f, 0.f);
        if (e >= 0) v = *(const float4*)(A + (size_t)e * H + k4);
        uint32_t h0, l0, h1, l1;
        split2(v.x, v.y, h0, l0);
        split2(v.z, v.w, h1, l1);
        uint32_t off = (uint32_t)m * TSTRIDE + (uint32_t)k4 * 2;
        *(uint2*)(sm + SM_AH + off) = make_uint2(h0, h1);
        *(uint2*)(sm + SM_AL + off) = make_uint2(l0, l1);
    }
}

__device__ __forceinline__ void copy_W(const char* __restrict__ wh, const char* __restrict__ wl,
                                       char* sm, int tid) {
#pragma unroll
    for (int it = 0; it < 8; ++it) {
        int idx = tid + it * 256;
        int row = idx >> 4;
        int chunk = idx & 15;
        uint32_t off = (uint32_t)row * TSTRIDE + (uint32_t)chunk * 16;
        *(uint4*)(sm + SM_WH + off) = ((const uint4*)wh)[idx];
        *(uint4*)(sm + SM_WL + off) = ((const uint4*)wl)[idx];
    }
}

// 3-term compensated HMMA: acc += Ah*Wh + Ah*Wl + Al*Wh  (warp tile 64x32)
__device__ __forceinline__ void gemm_hmma(uint32_t sb, int wm, int wn, int lane,
                                          float acc[4][4][4]) {
    uint32_t aRowBase = (uint32_t)(wm * 64 + (lane & 15)) * TSTRIDE + (uint32_t)(lane >> 4) * 16;
    uint32_t bRowBase = (uint32_t)(wn * 32 + (lane & 15)) * TSTRIDE + (uint32_t)(lane >> 4) * 16;
#pragma unroll
    for (int t = 0; t < 3; ++t) {
        uint32_t aBase = sb + (t == 2 ? SM_AL : SM_AH) + aRowBase;
        uint32_t wBase = sb + (t == 1 ? SM_WL : SM_WH) + bRowBase;
#pragma unroll
        for (int kf = 0; kf < 8; ++kf) {
            uint32_t af[4][4], bf[2][4];
#pragma unroll
            for (int mf = 0; mf < 4; ++mf)
                ldsm_x4(af[mf], aBase + mf * 16 * TSTRIDE + kf * 32);
#pragma unroll
            for (int p = 0; p < 2; ++p)
                ldsm_x4(bf[p], wBase + p * 16 * TSTRIDE + kf * 32);
#pragma unroll
            for (int mf = 0; mf < 4; ++mf) {
                mma16816(acc[mf][0], af[mf], bf[0][0], bf[0][2]);
                mma16816(acc[mf][1], af[mf], bf[0][1], bf[0][3]);
                mma16816(acc[mf][2], af[mf], bf[1][0], bf[1][2]);
                mma16816(acc[mf][3], af[mf], bf[1][1], bf[1][3]);
            }
        }
    }
}

// ---------------- index prep ----------------
__global__ void detect_idx(const long long* __restrict__ ei, int E, int N) {
    int i = blockIdx.x * blockDim.x + threadIdx.x;
    int stride = gridDim.x * blockDim.x;
    int bad = 0;
    for (int e = i; e < E; e += stride) {
        long long v = ei[e];
        if (v < 0 || v >= (long long)N) bad = 1;
    }
    if (__syncthreads_or(bad) && threadIdx.x == 0) atomicOr(&g_not64, 1);
}

__global__ void convert_idx(const void* __restrict__ ei, int E, int N,
                            int* __restrict__ row, int* __restrict__ col,
                            int* __restrict__ cnt) {
    int e = blockIdx.x * blockDim.x + threadIdx.x;
    if (e >= E) return;
    int r, c;
    if (g_not64) {
        const int* p = (const int*)ei;
        r = p[e]; c = p[E + e];
    } else {
        const long long* p = (const long long*)ei;
        r = (int)p[e]; c = (int)p[E + e];
    }
    r = min(max(r, 0), N - 1);
    c = min(max(c, 0), N - 1);
    row[e] = r;
    col[e] = c;
    atomicAdd(&cnt[c], 1);
}

// ---------------- 2-level exclusive scan + counting sort ----------------
__global__ void scan_a(const int* __restrict__ cnt, int* __restrict__ scan,
                       int* __restrict__ bsum, int N) {
    __shared__ int s[256];
    int t = threadIdx.x, i = blockIdx.x * 256 + t;
    int v = (i < N) ? cnt[i] : 0;
    s[t] = v;
    __syncthreads();
    for (int off = 1; off < 256; off <<= 1) {
        int x = (t >= off) ? s[t - off] : 0;
        __syncthreads();
        s[t] += x;
        __syncthreads();
    }
    if (i < N) scan[i] = s[t] - v;
    if (t == 255) bsum[blockIdx.x] = s[255];
}

__global__ void scan_b(int* __restrict__ bsum, int nb) {
    __shared__ int s[256];
    int t = threadIdx.x;
    int v = (t < nb) ? bsum[t] : 0;
    s[t] = v;
    __syncthreads();
    for (int off = 1; off < 256; off <<= 1) {
        int x = (t >= off) ? s[t - off] : 0;
        __syncthreads();
        s[t] += x;
        __syncthreads();
    }
    if (t < nb) bsum[t] = s[t] - v;
}

__global__ void scan_c(const int* __restrict__ scan, const int* __restrict__ bsum,
                       int* __restrict__ start, int N) {
    int i = blockIdx.x * blockDim.x + threadIdx.x;
    if (i < N) start[i] = scan[i] + bsum[i >> 8];
}

__global__ void scatter_sort(const int* __restrict__ col, int E,
                             int* __restrict__ start, int* __restrict__ sorted) {
    int e = blockIdx.x * blockDim.x + threadIdx.x;
    if (e < E) {
        int p = atomicAdd(&start[col[e]], 1);
        sorted[p] = e;
    }
}

// ---------------- weight preconvert ----------------
__global__ void prep_weights(const float* __restrict__ We1, const float* __restrict__ We2,
                             const float* __restrict__ Wn1, const float* __restrict__ Wn2) {
    int task = blockIdx.x * blockDim.x + threadIdx.x;
    if (task >= 7 * 4096) return;
    int t = task >> 12;
    int r = task & 4095;
    int n = r >> 5;
    int k4 = (r & 31) << 2;
    const float* src;
    switch (t) {
        case 0: src = We1;          break;
        case 1: src = We1 + 16384;  break;
        case 2: src = We1 + 32768;  break;
        case 3: src = We2;          break;
        case 4: src = Wn1;          break;
        case 5: src = Wn1 + 16384;  break;
        default: src = Wn2;         break;
    }
    float v0 = src[(k4 + 0) * H + n];
    float v1 = src[(k4 + 1) * H + n];
    float v2 = src[(k4 + 2) * H + n];
    float v3 = src[(k4 + 3) * H + n];
    uint32_t h0, l0, h1, l1;
    split2(v0, v1, h0, l0);
    split2(v2, v3, h1, l1);
    uint32_t off = (uint32_t)n * 256 + (uint32_t)k4 * 2;
    *(uint2*)(g_Wimg + (size_t)t * 32768 + off)       = make_uint2(h0, h1);
    *(uint2*)(g_Wimg + (size_t)(7 + t) * 32768 + off) = make_uint2(l0, l1);
}

// ---------------- node GEMM ----------------
template<bool DUAL, bool RELU, int BIAS_MODE>
__global__ void __launch_bounds__(256, 1)
node_gemm(const float* __restrict__ A1, const char* __restrict__ w1h, const char* __restrict__ w1l,
          const float* __restrict__ A2, const char* __restrict__ w2h, const char* __restrict__ w2l,
          const float* __restrict__ bias, const int* __restrict__ cnt,
          float* __restrict__ C, int M) {
    extern __shared__ char sm[];
    uint32_t sb = smem_u32(sm);
    int tid = threadIdx.x, lane = tid & 31, wid = tid >> 5;
    int wm = wid & 1, wn = wid >> 1;
    int gm = blockIdx.x * BM;

    float acc[4][4][4];
#pragma unroll
    for (int a = 0; a < 4; ++a)
#pragma unroll
        for (int b = 0; b < 4; ++b)
#pragma unroll
            for (int c = 0; c < 4; ++c) acc[a][b][c] = 0.f;

    load_convert_A(A1, gm, M, sm, tid);
    copy_W(w1h, w1l, sm, tid);
    __syncthreads();
    gemm_hmma(sb, wm, wn, lane, acc);
    if (DUAL) {
        __syncthreads();
        load_convert_A(A2, gm, M, sm, tid);
        copy_W(w2h, w2l, sm, tid);
        __syncthreads();
        gemm_hmma(sb, wm, wn, lane, acc);
    }

#pragma unroll
    for (int mf = 0; mf < 4; ++mf) {
        int r0 = gm + wm * 64 + mf * 16 + (lane >> 2);
        int r1 = r0 + 8;
        float d0 = 0.f, d1 = 0.f;
        if (BIAS_MODE == 2) {
            if (r0 < M) d0 = (float)cnt[r0];
            if (r1 < M) d1 = (float)cnt[r1];
        }
#pragma unroll
        for (int nf = 0; nf < 4; ++nf) {
            int c = wn * 32 + nf * 8 + (lane & 3) * 2;
            float bx = 0.f, by = 0.f;
            if (BIAS_MODE != 0) {
                float2 b = *(const float2*)(bias + c);
                bx = b.x; by = b.y;
            }
            if (r0 < M) {
                float vx = acc[mf][nf][0], vy = acc[mf][nf][1];
                if (BIAS_MODE == 1) { vx += bx; vy += by; }
                else if (BIAS_MODE == 2) { vx += d0 * bx; vy += d0 * by; }
                if (RELU) { vx = fmaxf(vx, 0.f); vy = fmaxf(vy, 0.f); }
                *(float2*)(C + (size_t)r0 * H + c) = make_float2(vx, vy);
            }
            if (r1 < M) {
                float vx = acc[mf][nf][2], vy = acc[mf][nf][3];
                if (BIAS_MODE == 1) { vx += bx; vy += by; }
                else if (BIAS_MODE == 2) { vx += d1 * bx; vy += d1 * by; }
                if (RELU) { vx = fmaxf(vx, 0.f); vy = fmaxf(vy, 0.f); }
                *(float2*)(C + (size_t)r1 * H + c) = make_float2(vx, vy);
            }
        }
    }
}

// ---------------- edge GEMM (sorted by col) ----------------
// h = relu(EA[eid]@We1c + P[row] + Q[col]); segment-sum over equal cols; red.v4 per segment
__global__ void __launch_bounds__(256, 1)
edge_gemm(const float* __restrict__ EA, const char* __restrict__ wh, const char* __restrict__ wl,
          const int* __restrict__ rowi, const int* __restrict__ coli,
          const int* __restrict__ sorted,
          const float* __restrict__ P, const float* __restrict__ Q,
          float* __restrict__ Hsum, int E) {
    extern __shared__ char sm[];
    uint32_t sb = smem_u32(sm);
    int tid = threadIdx.x, lane = tid & 31, wid = tid >> 5;
    int wm = wid & 1, wn = wid >> 1;
    int ge = blockIdx.x * BM;
    int* eid = (int*)(sm + SM_EID);
    int* rid = (int*)(sm + SM_RID);
    int* cid = (int*)(sm + SM_CID);

    if (tid < 128) {
        int pos = ge + tid;
        int e = (pos < E) ? sorted[pos] : -1;
        eid[tid] = e;
        rid[tid] = (e >= 0) ? rowi[e] : 0;
        cid[tid] = (e >= 0) ? coli[e] : -1;
    }
    copy_W(wh, wl, sm, tid);
    __syncthreads();                  // eid visible for gathered A load
    load_convert_A_gather(EA, eid, sm, tid);
    __syncthreads();

    float acc[4][4][4];
#pragma unroll
    for (int a = 0; a < 4; ++a)
#pragma unroll
        for (int b = 0; b < 4; ++b)
#pragma unroll
            for (int c = 0; c < 4; ++c) acc[a][b][c] = 0.f;
    gemm_hmma(sb, wm, wn, lane, acc);
    __syncthreads();                  // done reading W region; h-tile overlays it

    // epilogue: h = relu(acc + P[row] + Q[col]) -> smem h-tile
#pragma unroll
    for (int mf = 0; mf < 4; ++mf) {
        int li0 = wm * 64 + mf * 16 + (lane >> 2);
        int li1 = li0 + 8;
        int r0 = rid[li0], c0 = cid[li0];
        int r1 = rid[li1], c1 = cid[li1];
#pragma unroll
        for (int nf = 0; nf < 4; ++nf) {
            int c = wn * 32 + nf * 8 + (lane & 3) * 2;
            {
                int rr = max(r0, 0), cc = max(c0, 0);
                float2 pv = *(const float2*)(P + (size_t)rr * H + c);
                float2 qv = *(const float2*)(Q + (size_t)cc * H + c);
                float vx = fmaxf(acc[mf][nf][0] + pv.x + qv.x, 0.f);
                float vy = fmaxf(acc[mf][nf][1] + pv.y + qv.y, 0.f);
                *(float2*)(sm + SM_HT + (size_t)li0 * HTSTRIDE + c * 4) = make_float2(vx, vy);
            }
            {
                int rr = max(r1, 0), cc = max(c1, 0);
                float2 pv = *(const float2*)(P + (size_t)rr * H + c);
                float2 qv = *(const float2*)(Q + (size_t)cc * H + c);
                float vx = fmaxf(acc[mf][nf][2] + pv.x + qv.x, 0.f);
                float vy = fmaxf(acc[mf][nf][3] + pv.y + qv.y, 0.f);
                *(float2*)(sm + SM_HT + (size_t)li1 * HTSTRIDE + c * 4) = make_float2(vx, vy);
            }
        }
    }
    __syncthreads();

    // segment reduction: cols nondecreasing; walker w covers 16 edges, chunk q = 16B of the row
    int nvalid = min(128, E - ge);
    int w = tid >> 5, q = tid & 31;
    float4 s = make_float4(0.f, 0.f, 0.f, 0.f);
    int cur = -1;
#pragma unroll 4
    for (int i = 0; i < 16; ++i) {
        int e = w * 16 + i;
        if (e >= nvalid) break;
        int c = cid[e];
        if (c != cur) {
            if (cur >= 0) red_add_v4(Hsum + (size_t)cur * H + q * 4, s);
            s = make_float4(0.f, 0.f, 0.f, 0.f);
            cur = c;
        }
        float4 hv = *(const float4*)(sm + SM_HT + (size_t)e * HTSTRIDE + q * 16);
        s.x += hv.x; s.y += hv.y; s.z += hv.z; s.w += hv.w;
    }
    if (cur >= 0) red_add_v4(Hsum + (size_t)cur * H + q * 4, s);
}

__global__ void zero_kernel(float* __restrict__ hs, int* __restrict__ cnt, int nh, int nd) {
    int i = blockIdx.x * blockDim.x + threadIdx.x;
    if (i < nh) hs[i] = 0.f;
    if (i < nd) cnt[i] = 0;
    if (i == 0) g_not64 = 0;
}

// ---------------- host ----------------
extern "C" void kernel_launch(void* const* d_in, const int* in_sizes, int n_in,
                              void* d_out, int out_size) {
    const float* x   = (const float*)d_in[0];
    const void*  ei  = d_in[1];
    const float* ea  = (const float*)d_in[2];
    const float* We1 = (const float*)d_in[3];
    const float* be1 = (const float*)d_in[4];
    const float* We2 = (const float*)d_in[5];
    const float* be2 = (const float*)d_in[6];
    const float* Wn1 = (const float*)d_in[7];
    const float* bn1 = (const float*)d_in[8];
    const float* Wn2 = (const float*)d_in[9];
    const float* bn2 = (const float*)d_in[10];
    float* out = (float*)d_out;

    int N = in_sizes[0] / H;
    int E = in_sizes[1] / 2;

    void *pP, *pQ, *pHs, *pAgg, *pT, *pCnt, *pScan, *pBsum, *pStart, *pRow, *pCol, *pSort, *pWimg;
    cudaGetSymbolAddress(&pP, g_P);
    cudaGetSymbolAddress(&pQ, g_Q);
    cudaGetSymbolAddress(&pHs, g_Hsum);
    cudaGetSymbolAddress(&pAgg, g_agg);
    cudaGetSymbolAddress(&pT, g_Tbuf);
    cudaGetSymbolAddress(&pCnt, g_cnt);
    cudaGetSymbolAddress(&pScan, g_scan);
    cudaGetSymbolAddress(&pBsum, g_bsum);
    cudaGetSymbolAddress(&pStart, g_start);
    cudaGetSymbolAddress(&pRow, g_row);
    cudaGetSymbolAddress(&pCol, g_col);
    cudaGetSymbolAddress(&pSort, g_sorted);
    cudaGetSymbolAddress(&pWimg, g_Wimg);
    float* P    = (float*)pP;
    float* Q    = (float*)pQ;
    float* Hs   = (float*)pHs;
    float* agg  = (float*)pAgg;
    float* T    = (float*)pT;
    int*   cnt  = (int*)pCnt;
    int*   scn  = (int*)pScan;
    int*   bsm  = (int*)pBsum;
    int*   stt  = (int*)pStart;
    int*   ro   = (int*)pRow;
    int*   co   = (int*)pCol;
    int*   srt  = (int*)pSort;
    const char* W = (const char*)pWimg;
    auto wH = [&](int t) { return W + (size_t)t * 32768; };
    auto wL = [&](int t) { return W + (size_t)(7 + t) * 32768; };

    cudaFuncSetAttribute(node_gemm<false, false, 0>, cudaFuncAttributeMaxDynamicSharedMemorySize, SMEM_NODE);
    cudaFuncSetAttribute(node_gemm<false, false, 1>, cudaFuncAttributeMaxDynamicSharedMemorySize, SMEM_NODE);
    cudaFuncSetAttribute(node_gemm<false, false, 2>, cudaFuncAttributeMaxDynamicSharedMemorySize, SMEM_NODE);
    cudaFuncSetAttribute(node_gemm<true,  true,  1>, cudaFuncAttributeMaxDynamicSharedMemorySize, SMEM_NODE);
    cudaFuncSetAttribute(edge_gemm, cudaFuncAttributeMaxDynamicSharedMemorySize, SMEM_EDGE);

    int nodeBlocks = (N + BM - 1) / BM;
    int edgeBlocks = (E + BM - 1) / BM;
    int scanBlocks = (N + 255) / 256;
    int nh = N * H;

    // 0) zero
    zero_kernel<<<(nh + 255) / 256, 256>>>(Hs, cnt, nh, N);
    // 1) index prep: dtype sniff, normalize, histogram
    detect_idx<<<512, 256>>>((const long long*)ei, E, N);
    convert_idx<<<(E + 255) / 256, 256>>>(ei, E, N, ro, co, cnt);
    // 2) counting sort by col
    scan_a<<<scanBlocks, 256>>>(cnt, scn, bsm, N);
    scan_b<<<1, 256>>>(bsm, scanBlocks);
    scan_c<<<scanBlocks, 256>>>(scn, bsm, stt, N);
    scatter_sort<<<(E + 255) / 256, 256>>>(co, E, stt, srt);
    // 3) weights -> transposed + hi/lo split bf16 images
    prep_weights<<<112, 256>>>(We1, We2, Wn1, Wn2);
    // 4) P = x@We1a + be1 ; Q = x@We1b
    node_gemm<false, false, 1><<<nodeBlocks, 256, SMEM_NODE>>>(x, wH(0), wL(0), nullptr, nullptr, nullptr, be1, nullptr, P, N);
    node_gemm<false, false, 0><<<nodeBlocks, 256, SMEM_NODE>>>(x, wH(1), wL(1), nullptr, nullptr, nullptr, nullptr, nullptr, Q, N);
    // 5) edge: sorted tiles, segment-reduced scatter
    edge_gemm<<<edgeBlocks, 256, SMEM_EDGE>>>(ea, wH(2), wL(2), ro, co, srt, P, Q, Hs, E);
    // 6) agg = Hsum@We2 + deg*be2
    node_gemm<false, false, 2><<<nodeBlocks, 256, SMEM_NODE>>>(Hs, wH(3), wL(3), nullptr, nullptr, nullptr, be2, cnt, agg, N);
    // 7) T = relu(x@Wn1a + agg@Wn1b + bn1)
    node_gemm<true, true, 1><<<nodeBlocks, 256, SMEM_NODE>>>(x, wH(4), wL(4), agg, wH(5), wL(5), bn1, nullptr, T, N);
    // 8) out = T@Wn2 + bn2
    node_gemm<false, false, 1><<<nodeBlocks, 256, SMEM_NODE>>>(T, wH(6), wL(6), nullptr, nullptr, nullptr, bn2, nullptr, out, N);
}

// round 8
// speedup vs baseline: 1.1398x; 1.1398x over previous
#include <cuda_runtime.h>
#include <cuda_bf16.h>
#include <cstdint>

#define H 128
#define BM 64
#define MAXN 50176
#define MAXE 800000

// ---------------- scratch (device globals) ----------------
__device__ float g_P[MAXN * H];
__device__ float g_Q[MAXN * H];
__device__ float g_Hsum[MAXN * H];
__device__ float g_agg[MAXN * H];
__device__ float g_Tbuf[MAXN * H];
__device__ int   g_cnt[MAXN];        // in-degree
__device__ int   g_row[MAXE];
__device__ int   g_col[MAXE];
// 7 weight tiles x (hi,lo): B^T[n][k] bf16, packed 256B rows, 32KB each
__device__ __align__(16) char g_Wimg[14 * 32768];

// ---------------- smem layout (BM=64 A tiles, full 128-row W tiles) ----------------
#define ASTRIDE 272
#define ATILE   (64 * ASTRIDE)           // 17408
#define WTILE   (128 * ASTRIDE)          // 34816
#define SM_AH   0
#define SM_AL   ATILE
#define SM_WH   (2 * ATILE)
#define SM_WL   (2 * ATILE + WTILE)
#define SM_RID  (2 * ATILE + 2 * WTILE)  // 104448
#define SM_CID  (SM_RID + 256)
#define SMEM_NODE (2 * ATILE + 2 * WTILE)        // 104448
#define SMEM_EDGE (SM_CID + 256)                 // 104960

// ---------------- PTX helpers ----------------
__device__ __forceinline__ uint32_t smem_u32(const void* p) {
    uint32_t a;
    asm("{ .reg .u64 t; cvta.to.shared.u64 t, %1; cvt.u32.u64 %0, t; }" : "=r"(a) : "l"(p));
    return a;
}
__device__ __forceinline__ void ldsm_x4(uint32_t* r, uint32_t addr) {
    asm volatile("ldmatrix.sync.aligned.m8n8.x4.shared.b16 {%0,%1,%2,%3}, [%4];"
                 : "=r"(r[0]), "=r"(r[1]), "=r"(r[2]), "=r"(r[3]) : "r"(addr));
}
__device__ __forceinline__ void mma16816(float* d, const uint32_t* a, uint32_t b0, uint32_t b1) {
    asm volatile("mma.sync.aligned.m16n8k16.row.col.f32.bf16.bf16.f32 "
                 "{%0,%1,%2,%3}, {%4,%5,%6,%7}, {%8,%9}, {%0,%1,%2,%3};"
                 : "+f"(d[0]), "+f"(d[1]), "+f"(d[2]), "+f"(d[3])
                 : "r"(a[0]), "r"(a[1]), "r"(a[2]), "r"(a[3]), "r"(b0), "r"(b1));
}
__device__ __forceinline__ void red_add_v4(float* p, float4 v) {
    asm volatile("red.global.add.v4.f32 [%0], {%1,%2,%3,%4};"
                 :: "l"(p), "f"(v.x), "f"(v.y), "f"(v.z), "f"(v.w) : "memory");
}

__device__ __forceinline__ void split2(float a, float b, uint32_t& hi, uint32_t& lo) {
    __nv_bfloat16 ha = __float2bfloat16_rn(a), hb = __float2bfloat16_rn(b);
    float ra = a - __bfloat162float(ha), rb = b - __bfloat162float(hb);
    __nv_bfloat16 la = __float2bfloat16_rn(ra), lb = __float2bfloat16_rn(rb);
    hi = ((uint32_t)*(uint16_t*)&hb << 16) | (uint32_t)*(uint16_t*)&ha;
    lo = ((uint32_t)*(uint16_t*)&lb << 16) | (uint32_t)*(uint16_t*)&la;
}

// load fp32 A tile (64 rows), split to bf16 hi/lo smem tiles
__device__ __forceinline__ void load_convert_A(const float* __restrict__ A, int gm, int M,
                                               char* sm, int tid) {
#pragma unroll
    for (int it = 0; it < 8; ++it) {
        int idx = tid + it * 256;              // 0..2047
        int m = idx >> 5;
        int k4 = (idx & 31) << 2;
        float4 v = make_float4(0.f, 0.f, 0.f, 0.f);
        int gr = gm + m;
        if (gr < M) v = *(const float4*)(A + (size_t)gr * H + k4);
        uint32_t h0, l0, h1, l1;
        split2(v.x, v.y, h0, l0);
        split2(v.z, v.w, h1, l1);
        uint32_t off = (uint32_t)m * ASTRIDE + (uint32_t)k4 * 2;
        *(uint2*)(sm + SM_AH + off) = make_uint2(h0, h1);
        *(uint2*)(sm + SM_AL + off) = make_uint2(l0, l1);
    }
}

__device__ __forceinline__ void copy_W(const char* __restrict__ wh, const char* __restrict__ wl,
                                       char* sm, int tid) {
#pragma unroll
    for (int it = 0; it < 8; ++it) {
        int idx = tid + it * 256;              // 0..2047
        int row = idx >> 4;
        int chunk = idx & 15;
        uint32_t off = (uint32_t)row * ASTRIDE + (uint32_t)chunk * 16;
        *(uint4*)(sm + SM_WH + off) = ((const uint4*)wh)[idx];
        *(uint4*)(sm + SM_WL + off) = ((const uint4*)wl)[idx];
    }
}

// 3-term compensated HMMA: acc += Ah*Wh + Ah*Wl + Al*Wh   (warp tile 32x32)
__device__ __forceinline__ void gemm_hmma(uint32_t sb, int wm, int wn, int lane,
                                          float acc[2][4][4]) {
    uint32_t aRowBase = (uint32_t)(wm * 32 + (lane & 15)) * ASTRIDE + (uint32_t)(lane >> 4) * 16;
    uint32_t bRowBase = (uint32_t)(wn * 32 + (lane & 15)) * ASTRIDE + (uint32_t)(lane >> 4) * 16;
#pragma unroll
    for (int t = 0; t < 3; ++t) {
        uint32_t aBase = sb + (t == 2 ? SM_AL : SM_AH) + aRowBase;
        uint32_t wBase = sb + (t == 1 ? SM_WL : SM_WH) + bRowBase;
#pragma unroll
        for (int kf = 0; kf < 8; ++kf) {
            uint32_t af[2][4], bf[2][4];
#pragma unroll
            for (int mf = 0; mf < 2; ++mf)
                ldsm_x4(af[mf], aBase + mf * 16 * ASTRIDE + kf * 32);
#pragma unroll
            for (int p = 0; p < 2; ++p)
                ldsm_x4(bf[p], wBase + p * 16 * ASTRIDE + kf * 32);
#pragma unroll
            for (int mf = 0; mf < 2; ++mf) {
                mma16816(acc[mf][0], af[mf], bf[0][0], bf[0][2]);
                mma16816(acc[mf][1], af[mf], bf[0][1], bf[0][3]);
                mma16816(acc[mf][2], af[mf], bf[1][0], bf[1][2]);
                mma16816(acc[mf][3], af[mf], bf[1][1], bf[1][3]);
            }
        }
    }
}

// ---------------- launch 0: zero buffers ----------------
__global__ void prep_zero(float* __restrict__ hs, int* __restrict__ cnt, int nh, int nd) {
    int i = blockIdx.x * blockDim.x + threadIdx.x;
    if (i < nh) hs[i] = 0.f;
    if (i < nd) cnt[i] = 0;
}

// ---------------- launch 1: convert idx (per-block dtype sniff) + weight prep ----------------
__device__ __forceinline__ void split_store_w(int t, int n, int k4,
                                              float v0, float v1, float v2, float v3) {
    uint32_t h0, l0, h1, l1;
    split2(v0, v1, h0, l0);
    split2(v2, v3, h1, l1);
    uint32_t off = (uint32_t)n * 256 + (uint32_t)k4 * 2;
    *(uint2*)(g_Wimg + (size_t)t * 32768 + off)       = make_uint2(h0, h1);
    *(uint2*)(g_Wimg + (size_t)(7 + t) * 32768 + off) = make_uint2(l0, l1);
}

__global__ void prep_idx_w(const void* __restrict__ ei, int E, int N, int cBlocks,
                           int* __restrict__ row, int* __restrict__ col,
                           int* __restrict__ cnt,
                           const float* __restrict__ We1, const float* __restrict__ We2,
                           const float* __restrict__ Wn1, const float* __restrict__ Wn2) {
    int tid = threadIdx.x;
    if ((int)blockIdx.x < cBlocks) {
        // per-block dtype sniff: read first 256 int64 slots (buffer >= E*4*2 bytes,
        // E >= 256). Genuine int64 indices all lie in [0,N); int32 data reinterpreted
        // as int64 fuses pairs into huge values -> every block reaches the same verdict.
        const long long* p64 = (const long long*)ei;
        long long sv = p64[tid];
        int not64 = __syncthreads_or((sv < 0) | (sv >= (long long)N));
        int e = blockIdx.x * 256 + tid;
        if (e < E) {
            int r, c;
            if (not64) {
                const int* p = (const int*)ei;
                r = p[e]; c = p[E + e];
            } else {
                r = (int)p64[e]; c = (int)p64[(size_t)E + e];
            }
            r = min(max(r, 0), N - 1);
            c = min(max(c, 0), N - 1);
            row[e] = r;
            col[e] = c;
            atomicAdd(&cnt[c], 1);
        }
    } else {
        int task = ((int)blockIdx.x - cBlocks) * 256 + tid;   // 7*4096 tasks
        if (task >= 7 * 4096) return;
        int t = task >> 12;
        int r = task & 4095;
        int n = r >> 5;
        int k4 = (r & 31) << 2;
        const float* src;
        switch (t) {
            case 0: src = We1;          break;
            case 1: src = We1 + 16384;  break;
            case 2: src = We1 + 32768;  break;
            case 3: src = We2;          break;
            case 4: src = Wn1;          break;
            case 5: src = Wn1 + 16384;  break;
            default: src = Wn2;         break;
        }
        split_store_w(t, n, k4,
                      src[(k4 + 0) * H + n], src[(k4 + 1) * H + n],
                      src[(k4 + 2) * H + n], src[(k4 + 3) * H + n]);
    }
}

// ---------------- launch 2: fused P & Q GEMM (gridDim.y selects) ----------------
__global__ void __launch_bounds__(256, 2)
node_pq(const float* __restrict__ x,
        const char* __restrict__ w0h, const char* __restrict__ w0l,
        const char* __restrict__ w1h, const char* __restrict__ w1l,
        const float* __restrict__ be1,
        float* __restrict__ P, float* __restrict__ Q, int M) {
    extern __shared__ char sm[];
    uint32_t sb = smem_u32(sm);
    int tid = threadIdx.x, lane = tid & 31, wid = tid >> 5;
    int wm = wid & 1, wn = wid >> 1;
    int gm = blockIdx.x * BM;
    bool isQ = (blockIdx.y != 0);
    const char* wh = isQ ? w1h : w0h;
    const char* wl = isQ ? w1l : w0l;
    float* C = isQ ? Q : P;

    float acc[2][4][4];
#pragma unroll
    for (int a = 0; a < 2; ++a)
#pragma unroll
        for (int b = 0; b < 4; ++b)
#pragma unroll
            for (int c = 0; c < 4; ++c) acc[a][b][c] = 0.f;

    load_convert_A(x, gm, M, sm, tid);
    copy_W(wh, wl, sm, tid);
    __syncthreads();
    gemm_hmma(sb, wm, wn, lane, acc);

    int gid = lane >> 2, tig = lane & 3;
#pragma unroll
    for (int mf = 0; mf < 2; ++mf) {
        int r0 = gm + wm * 32 + mf * 16 + gid;
        int r1 = r0 + 8;
#pragma unroll
        for (int nf = 0; nf < 4; ++nf) {
            int c = wn * 32 + nf * 8 + tig * 2;
            float bx = 0.f, by = 0.f;
            if (!isQ) {
                float2 b = *(const float2*)(be1 + c);
                bx = b.x; by = b.y;
            }
            if (r0 < M)
                *(float2*)(C + (size_t)r0 * H + c) =
                    make_float2(acc[mf][nf][0] + bx, acc[mf][nf][1] + by);
            if (r1 < M)
                *(float2*)(C + (size_t)r1 * H + c) =
                    make_float2(acc[mf][nf][2] + bx, acc[mf][nf][3] + by);
        }
    }
}

// ---------------- launch 3: edge GEMM ----------------
// h = relu(EA@We1c + P[row] + Q[col]); Hsum[col] += h  (red.v4 via shfl pairing)
__global__ void __launch_bounds__(256, 2)
edge_gemm(const float* __restrict__ EA, const char* __restrict__ wh, const char* __restrict__ wl,
          const int* __restrict__ rowi, const int* __restrict__ coli,
          const float* __restrict__ P, const float* __restrict__ Q,
          float* __restrict__ Hsum, int E) {
    extern __shared__ char sm[];
    uint32_t sb = smem_u32(sm);
    int tid = threadIdx.x, lane = tid & 31, wid = tid >> 5;
    int wm = wid & 1, wn = wid >> 1;
    int ge = blockIdx.x * BM;
    int* rid = (int*)(sm + SM_RID);
    int* cid = (int*)(sm + SM_CID);

    if (tid < 64) {
        int e = ge + tid;
        rid[tid] = (e < E) ? rowi[e] : 0;
        cid[tid] = (e < E) ? coli[e] : 0;
    }
    load_convert_A(EA, ge, E, sm, tid);
    copy_W(wh, wl, sm, tid);
    __syncthreads();

    float acc[2][4][4];
#pragma unroll
    for (int a = 0; a < 2; ++a)
#pragma unroll
        for (int b = 0; b < 4; ++b)
#pragma unroll
            for (int c = 0; c < 4; ++c) acc[a][b][c] = 0.f;
    gemm_hmma(sb, wm, wn, lane, acc);

    // epilogue: shfl-pair fragments into float4 rows; gather P/Q; relu; red.v4
    int gid = lane >> 2, tig = lane & 3;
    int odd = tig & 1;
#pragma unroll
    for (int mf = 0; mf < 2; ++mf) {
        int rl = wm * 32 + mf * 16 + gid + (odd << 3);   // local edge row this lane owns
        int e = ge + rl;
        int r = rid[rl], c = cid[rl];
        bool ok = (e < E);
#pragma unroll
        for (int nf = 0; nf < 4; ++nf) {
            // even tig sends its (c2,c3) [partner's row]; odd sends its (c0,c1)
            float sA = odd ? acc[mf][nf][0] : acc[mf][nf][2];
            float sB = odd ? acc[mf][nf][1] : acc[mf][nf][3];
            float rA = __shfl_xor_sync(0xffffffffu, sA, 1);
            float rB = __shfl_xor_sync(0xffffffffu, sB, 1);
            float4 v;
            if (odd) v = make_float4(rA, rB, acc[mf][nf][2], acc[mf][nf][3]);
            else     v = make_float4(acc[mf][nf][0], acc[mf][nf][1], rA, rB);
            int cb = wn * 32 + nf * 8 + (tig & 2) * 2;
            if (ok) {
                float4 pv = *(const float4*)(P + (size_t)r * H + cb);
                float4 qv = *(const float4*)(Q + (size_t)c * H + cb);
                v.x = fmaxf(v.x + pv.x + qv.x, 0.f);
                v.y = fmaxf(v.y + pv.y + qv.y, 0.f);
                v.z = fmaxf(v.z + pv.z + qv.z, 0.f);
                v.w = fmaxf(v.w + pv.w + qv.w, 0.f);
                red_add_v4(Hsum + (size_t)c * H + cb, v);
            }
        }
    }
}

// ---------------- launches 4-6: node GEMMs ----------------
// BIAS_MODE: 0 = none, 1 = +bias[n], 2 = +cnt[m]*bias[n]
template<bool DUAL, bool RELU, int BIAS_MODE>
__global__ void __launch_bounds__(256, 2)
node_gemm(const float* __restrict__ A1, const char* __restrict__ w1h, const char* __restrict__ w1l,
          const float* __restrict__ A2, const char* __restrict__ w2h, const char* __restrict__ w2l,
          const float* __restrict__ bias, const int* __restrict__ cnt,
          float* __restrict__ C, int M) {
    extern __shared__ char sm[];
    uint32_t sb = smem_u32(sm);
    int tid = threadIdx.x, lane = tid & 31, wid = tid >> 5;
    int wm = wid & 1, wn = wid >> 1;
    int gm = blockIdx.x * BM;

    float acc[2][4][4];
#pragma unroll
    for (int a = 0; a < 2; ++a)
#pragma unroll
        for (int b = 0; b < 4; ++b)
#pragma unroll
            for (int c = 0; c < 4; ++c) acc[a][b][c] = 0.f;

    load_convert_A(A1, gm, M, sm, tid);
    copy_W(w1h, w1l, sm, tid);
    __syncthreads();
    gemm_hmma(sb, wm, wn, lane, acc);
    if (DUAL) {
        __syncthreads();
        load_convert_A(A2, gm, M, sm, tid);
        copy_W(w2h, w2l, sm, tid);
        __syncthreads();
        gemm_hmma(sb, wm, wn, lane, acc);
    }

    int gid = lane >> 2, tig = lane & 3;
#pragma unroll
    for (int mf = 0; mf < 2; ++mf) {
        int r0 = gm + wm * 32 + mf * 16 + gid;
        int r1 = r0 + 8;
        float d0 = 0.f, d1 = 0.f;
        if (BIAS_MODE == 2) {
            if (r0 < M) d0 = (float)cnt[r0];
            if (r1 < M) d1 = (float)cnt[r1];
        }
#pragma unroll
        for (int nf = 0; nf < 4; ++nf) {
            int c = wn * 32 + nf * 8 + tig * 2;
            float bx = 0.f, by = 0.f;
            if (BIAS_MODE != 0) {
                float2 b = *(const float2*)(bias + c);
                bx = b.x; by = b.y;
            }
            if (r0 < M) {
                float vx = acc[mf][nf][0], vy = acc[mf][nf][1];
                if (BIAS_MODE == 1) { vx += bx; vy += by; }
                else if (BIAS_MODE == 2) { vx += d0 * bx; vy += d0 * by; }
                if (RELU) { vx = fmaxf(vx, 0.f); vy = fmaxf(vy, 0.f); }
                *(float2*)(C + (size_t)r0 * H + c) = make_float2(vx, vy);
            }
            if (r1 < M) {
                float vx = acc[mf][nf][2], vy = acc[mf][nf][3];
                if (BIAS_MODE == 1) { vx += bx; vy += by; }
                else if (BIAS_MODE == 2) { vx += d1 * bx; vy += d1 * by; }
                if (RELU) { vx = fmaxf(vx, 0.f); vy = fmaxf(vy, 0.f); }
                *(float2*)(C + (size_t)r1 * H + c) = make_float2(vx, vy);
            }
        }
    }
}

// ---------------- host ----------------
extern "C" void kernel_launch(void* const* d_in, const int* in_sizes, int n_in,
                              void* d_out, int out_size) {
    const float* x   = (const float*)d_in[0];
    const void*  ei  = d_in[1];
    const float* ea  = (const float*)d_in[2];
    const float* We1 = (const float*)d_in[3];
    const float* be1 = (const float*)d_in[4];
    const float* We2 = (const float*)d_in[5];
    const float* be2 = (const float*)d_in[6];
    const float* Wn1 = (const float*)d_in[7];
    const float* bn1 = (const float*)d_in[8];
    const float* Wn2 = (const float*)d_in[9];
    const float* bn2 = (const float*)d_in[10];
    float* out = (float*)d_out;

    int N = in_sizes[0] / H;
    int E = in_sizes[1] / 2;

    void *pP, *pQ, *pHs, *pAgg, *pT, *pCnt, *pRow, *pCol, *pWimg;
    cudaGetSymbolAddress(&pP, g_P);
    cudaGetSymbolAddress(&pQ, g_Q);
    cudaGetSymbolAddress(&pHs, g_Hsum);
    cudaGetSymbolAddress(&pAgg, g_agg);
    cudaGetSymbolAddress(&pT, g_Tbuf);
    cudaGetSymbolAddress(&pCnt, g_cnt);
    cudaGetSymbolAddress(&pRow, g_row);
    cudaGetSymbolAddress(&pCol, g_col);
    cudaGetSymbolAddress(&pWimg, g_Wimg);
    float* P   = (float*)pP;
    float* Q   = (float*)pQ;
    float* Hs  = (float*)pHs;
    float* agg = (float*)pAgg;
    float* T   = (float*)pT;
    int*   cnt = (int*)pCnt;
    int*   ro  = (int*)pRow;
    int*   co  = (int*)pCol;
    const char* W = (const char*)pWimg;
    auto wH = [&](int t) { return W + (size_t)t * 32768; };
    auto wL = [&](int t) { return W + (size_t)(7 + t) * 32768; };

    cudaFuncSetAttribute(node_pq, cudaFuncAttributeMaxDynamicSharedMemorySize, SMEM_NODE);
    cudaFuncSetAttribute(edge_gemm, cudaFuncAttributeMaxDynamicSharedMemorySize, SMEM_EDGE);
    cudaFuncSetAttribute(node_gemm<false, false, 1>, cudaFuncAttributeMaxDynamicSharedMemorySize, SMEM_NODE);
    cudaFuncSetAttribute(node_gemm<false, false, 2>, cudaFuncAttributeMaxDynamicSharedMemorySize, SMEM_NODE);
    cudaFuncSetAttribute(node_gemm<true,  true,  1>, cudaFuncAttributeMaxDynamicSharedMemorySize, SMEM_NODE);

    int nodeBlocks = (N + BM - 1) / BM;              // 782
    int edgeBlocks = (E + BM - 1) / BM;              // 12500
    int nh = N * H;
    int cBlocks = (E + 255) / 256;                   // 3125

    // launch 0: zero Hsum + cnt
    prep_zero<<<(nh + 255) / 256, 256>>>(Hs, cnt, nh, N);
    // launch 1: idx convert (per-block dtype sniff) + weight images
    prep_idx_w<<<cBlocks + 112, 256>>>(ei, E, N, cBlocks, ro, co, cnt, We1, We2, Wn1, Wn2);
    // launch 2: P = x@We1a + be1  AND  Q = x@We1b   (gridDim.y=2)
    node_pq<<<dim3(nodeBlocks, 2), 256, SMEM_NODE>>>(x, wH(0), wL(0), wH(1), wL(1), be1, P, Q, N);
    // launch 3 (ncu capture slot): edge GEMM + scatter
    edge_gemm<<<edgeBlocks, 256, SMEM_EDGE>>>(ea, wH(2), wL(2), ro, co, P, Q, Hs, E);
    // launch 4: agg = Hsum@We2 + deg*be2
    node_gemm<false, false, 2><<<nodeBlocks, 256, SMEM_NODE>>>(Hs, wH(3), wL(3), nullptr, nullptr, nullptr, be2, cnt, agg, N);
    // launch 5: T = relu(x@Wn1a + agg@Wn1b + bn1)
    node_gemm<true, true, 1><<<nodeBlocks, 256, SMEM_NODE>>>(x, wH(4), wL(4), agg, wH(5), wL(5), bn1, nullptr, T, N);
    // launch 6: out = T@Wn2 + bn2
    node_gemm<false, false, 1><<<nodeBlocks, 256, SMEM_NODE>>>(T, wH(6), wL(6), nullptr, nullptr, nullptr, bn2, nullptr, out, N);
}

// round 10
// speedup vs baseline: 1.1877x; 1.0421x over previous
#include <cuda_runtime.h>
#include <cuda_bf16.h>
#include <cstdint>

#define H 128
#define BM 64
#define MAXN 50176
#define MAXE 800000

// ---------------- scratch (device globals) ----------------
__device__ float g_P[MAXN * H];
__device__ float g_Q[MAXN * H];
__device__ float g_Hsum[MAXN * H];
__device__ float g_agg[MAXN * H];
__device__ float g_Tbuf[MAXN * H];
__device__ int   g_cnt[MAXN];        // in-degree
__device__ int   g_row[MAXE];
__device__ int   g_col[MAXE];
// 7 weight tiles x (hi,lo): B^T[n][k] bf16, packed 256B rows, 32KB each
__device__ __align__(16) char g_Wimg[14 * 32768];

// ---------------- smem layout (BM=64 A tiles, full 128-row W tiles) ----------------
#define ASTRIDE 272
#define ATILE   (64 * ASTRIDE)           // 17408
#define WTILE   (128 * ASTRIDE)          // 34816
#define SM_AH   0
#define SM_AL   ATILE
#define SM_WH   (2 * ATILE)
#define SM_WL   (2 * ATILE + WTILE)
#define SM_RID  (2 * ATILE + 2 * WTILE)  // 104448
#define SM_CID  (SM_RID + 256)
#define SMEM_NODE (2 * ATILE + 2 * WTILE)        // 104448
#define SMEM_EDGE (SM_CID + 256)                 // 104960

// ---------------- PTX helpers ----------------
__device__ __forceinline__ uint32_t smem_u32(const void* p) {
    uint32_t a;
    asm("{ .reg .u64 t; cvta.to.shared.u64 t, %1; cvt.u32.u64 %0, t; }" : "=r"(a) : "l"(p));
    return a;
}
__device__ __forceinline__ void ldsm_x4(uint32_t* r, uint32_t addr) {
    asm volatile("ldmatrix.sync.aligned.m8n8.x4.shared.b16 {%0,%1,%2,%3}, [%4];"
                 : "=r"(r[0]), "=r"(r[1]), "=r"(r[2]), "=r"(r[3]) : "r"(addr));
}
__device__ __forceinline__ void mma16816(float* d, const uint32_t* a, uint32_t b0, uint32_t b1) {
    asm volatile("mma.sync.aligned.m16n8k16.row.col.f32.bf16.bf16.f32 "
                 "{%0,%1,%2,%3}, {%4,%5,%6,%7}, {%8,%9}, {%0,%1,%2,%3};"
                 : "+f"(d[0]), "+f"(d[1]), "+f"(d[2]), "+f"(d[3])
                 : "r"(a[0]), "r"(a[1]), "r"(a[2]), "r"(a[3]), "r"(b0), "r"(b1));
}
__device__ __forceinline__ void red_add_v4(float* p, float4 v) {
    asm volatile("red.global.add.v4.f32 [%0], {%1,%2,%3,%4};"
                 :: "l"(p), "f"(v.x), "f"(v.y), "f"(v.z), "f"(v.w) : "memory");
}

__device__ __forceinline__ void split2(float a, float b, uint32_t& hi, uint32_t& lo) {
    __nv_bfloat16 ha = __float2bfloat16_rn(a), hb = __float2bfloat16_rn(b);
    float ra = a - __bfloat162float(ha), rb = b - __bfloat162float(hb);
    __nv_bfloat16 la = __float2bfloat16_rn(ra), lb = __float2bfloat16_rn(rb);
    hi = ((uint32_t)*(uint16_t*)&hb << 16) | (uint32_t)*(uint16_t*)&ha;
    lo = ((uint32_t)*(uint16_t*)&lb << 16) | (uint32_t)*(uint16_t*)&la;
}

// load fp32 A tile (64 rows), split to bf16 hi/lo smem tiles (direct path)
__device__ __forceinline__ void load_convert_A(const float* __restrict__ A, int gm, int M,
                                               char* sm, int tid) {
#pragma unroll
    for (int it = 0; it < 8; ++it) {
        int idx = tid + it * 256;              // 0..2047
        int m = idx >> 5;
        int k4 = (idx & 31) << 2;
        float4 v = make_float4(0.f, 0.f, 0.f, 0.f);
        int gr = gm + m;
        if (gr < M) v = *(const float4*)(A + (size_t)gr * H + k4);
        uint32_t h0, l0, h1, l1;
        split2(v.x, v.y, h0, l0);
        split2(v.z, v.w, h1, l1);
        uint32_t off = (uint32_t)m * ASTRIDE + (uint32_t)k4 * 2;
        *(uint2*)(sm + SM_AH + off) = make_uint2(h0, h1);
        *(uint2*)(sm + SM_AL + off) = make_uint2(l0, l1);
    }
}

// pipelined variants: fetch A into regs, convert+store later
__device__ __forceinline__ void fetch_A(const float* __restrict__ A, int gm, int M,
                                        float4* v, int tid) {
#pragma unroll
    for (int it = 0; it < 8; ++it) {
        int idx = tid + it * 256;
        int m = idx >> 5;
        int k4 = (idx & 31) << 2;
        int gr = gm + m;
        v[it] = (gr < M) ? *(const float4*)(A + (size_t)gr * H + k4)
                         : make_float4(0.f, 0.f, 0.f, 0.f);
    }
}
__device__ __forceinline__ void store_A(const float4* v, char* sm, int tid) {
#pragma unroll
    for (int it = 0; it < 8; ++it) {
        int idx = tid + it * 256;
        int m = idx >> 5;
        int k4 = (idx & 31) << 2;
        uint32_t h0, l0, h1, l1;
        split2(v[it].x, v[it].y, h0, l0);
        split2(v[it].z, v[it].w, h1, l1);
        uint32_t off = (uint32_t)m * ASTRIDE + (uint32_t)k4 * 2;
        *(uint2*)(sm + SM_AH + off) = make_uint2(h0, h1);
        *(uint2*)(sm + SM_AL + off) = make_uint2(l0, l1);
    }
}

__device__ __forceinline__ void copy_W(const char* __restrict__ wh, const char* __restrict__ wl,
                                       char* sm, int tid) {
#pragma unroll
    for (int it = 0; it < 8; ++it) {
        int idx = tid + it * 256;              // 0..2047
        int row = idx >> 4;
        int chunk = idx & 15;
        uint32_t off = (uint32_t)row * ASTRIDE + (uint32_t)chunk * 16;
        *(uint4*)(sm + SM_WH + off) = ((const uint4*)wh)[idx];
        *(uint4*)(sm + SM_WL + off) = ((const uint4*)wl)[idx];
    }
}

// 3-term compensated HMMA: acc += Ah*Wh + Ah*Wl + Al*Wh   (warp tile 32x32)
__device__ __forceinline__ void gemm_hmma(uint32_t sb, int wm, int wn, int lane,
                                          float acc[2][4][4]) {
    uint32_t aRowBase = (uint32_t)(wm * 32 + (lane & 15)) * ASTRIDE + (uint32_t)(lane >> 4) * 16;
    uint32_t bRowBase = (uint32_t)(wn * 32 + (lane & 15)) * ASTRIDE + (uint32_t)(lane >> 4) * 16;
#pragma unroll
    for (int t = 0; t < 3; ++t) {
        uint32_t aBase = sb + (t == 2 ? SM_AL : SM_AH) + aRowBase;
        uint32_t wBase = sb + (t == 1 ? SM_WL : SM_WH) + bRowBase;
#pragma unroll
        for (int kf = 0; kf < 8; ++kf) {
            uint32_t af[2][4], bf[2][4];
#pragma unroll
            for (int mf = 0; mf < 2; ++mf)
                ldsm_x4(af[mf], aBase + mf * 16 * ASTRIDE + kf * 32);
#pragma unroll
            for (int p = 0; p < 2; ++p)
                ldsm_x4(bf[p], wBase + p * 16 * ASTRIDE + kf * 32);
#pragma unroll
            for (int mf = 0; mf < 2; ++mf) {
                mma16816(acc[mf][0], af[mf], bf[0][0], bf[0][2]);
                mma16816(acc[mf][1], af[mf], bf[0][1], bf[0][3]);
                mma16816(acc[mf][2], af[mf], bf[1][0], bf[1][2]);
                mma16816(acc[mf][3], af[mf], bf[1][1], bf[1][3]);
            }
        }
    }
}

// ---------------- launch 0: zero buffers ----------------
__global__ void prep_zero(float* __restrict__ hs, int* __restrict__ cnt, int nh, int nd) {
    int i = blockIdx.x * blockDim.x + threadIdx.x;
    if (i < nh) hs[i] = 0.f;
    if (i < nd) cnt[i] = 0;
}

// ---------------- launch 1: convert idx (per-block dtype sniff) + weight prep ----------------
__device__ __forceinline__ void split_store_w(int t, int n, int k4,
                                              float v0, float v1, float v2, float v3) {
    uint32_t h0, l0, h1, l1;
    split2(v0, v1, h0, l0);
    split2(v2, v3, h1, l1);
    uint32_t off = (uint32_t)n * 256 + (uint32_t)k4 * 2;
    *(uint2*)(g_Wimg + (size_t)t * 32768 + off)       = make_uint2(h0, h1);
    *(uint2*)(g_Wimg + (size_t)(7 + t) * 32768 + off) = make_uint2(l0, l1);
}

__global__ void prep_idx_w(const void* __restrict__ ei, int E, int N, int cBlocks,
                           int* __restrict__ row, int* __restrict__ col,
                           int* __restrict__ cnt,
                           const float* __restrict__ We1, const float* __restrict__ We2,
                           const float* __restrict__ Wn1, const float* __restrict__ Wn2) {
    int tid = threadIdx.x;
    if ((int)blockIdx.x < cBlocks) {
        // per-block dtype sniff (see R8 comment): int32 data read as int64 fuses
        // index pairs into huge values -> every block reaches the same verdict.
        const long long* p64 = (const long long*)ei;
        long long sv = p64[tid];
        int not64 = __syncthreads_or((sv < 0) | (sv >= (long long)N));
        int e = blockIdx.x * 256 + tid;
        if (e < E) {
            int r, c;
            if (not64) {
                const int* p = (const int*)ei;
                r = p[e]; c = p[E + e];
            } else {
                r = (int)p64[e]; c = (int)p64[(size_t)E + e];
            }
            r = min(max(r, 0), N - 1);
            c = min(max(c, 0), N - 1);
            row[e] = r;
            col[e] = c;
            atomicAdd(&cnt[c], 1);
        }
    } else {
        int task = ((int)blockIdx.x - cBlocks) * 256 + tid;   // 7*4096 tasks
        if (task >= 7 * 4096) return;
        int t = task >> 12;
        int r = task & 4095;
        int n = r >> 5;
        int k4 = (r & 31) << 2;
        const float* src;
        switch (t) {
            case 0: src = We1;          break;
            case 1: src = We1 + 16384;  break;
            case 2: src = We1 + 32768;  break;
            case 3: src = We2;          break;
            case 4: src = Wn1;          break;
            case 5: src = Wn1 + 16384;  break;
            default: src = Wn2;         break;
        }
        split_store_w(t, n, k4,
                      src[(k4 + 0) * H + n], src[(k4 + 1) * H + n],
                      src[(k4 + 2) * H + n], src[(k4 + 3) * H + n]);
    }
}

// ---------------- launch 2: fused P & Q GEMM (gridDim.y selects) ----------------
__global__ void __launch_bounds__(256, 2)
node_pq(const float* __restrict__ x,
        const char* __restrict__ w0h, const char* __restrict__ w0l,
        const char* __restrict__ w1h, const char* __restrict__ w1l,
        const float* __restrict__ be1,
        float* __restrict__ P, float* __restrict__ Q, int M) {
    extern __shared__ char sm[];
    uint32_t sb = smem_u32(sm);
    int tid = threadIdx.x, lane = tid & 31, wid = tid >> 5;
    int wm = wid & 1, wn = wid >> 1;
    int gm = blockIdx.x * BM;
    bool isQ = (blockIdx.y != 0);
    const char* wh = isQ ? w1h : w0h;
    const char* wl = isQ ? w1l : w0l;
    float* C = isQ ? Q : P;

    float acc[2][4][4];
#pragma unroll
    for (int a = 0; a < 2; ++a)
#pragma unroll
        for (int b = 0; b < 4; ++b)
#pragma unroll
            for (int c = 0; c < 4; ++c) acc[a][b][c] = 0.f;

    load_convert_A(x, gm, M, sm, tid);
    copy_W(wh, wl, sm, tid);
    __syncthreads();
    gemm_hmma(sb, wm, wn, lane, acc);

    int gid = lane >> 2, tig = lane & 3;
#pragma unroll
    for (int mf = 0; mf < 2; ++mf) {
        int r0 = gm + wm * 32 + mf * 16 + gid;
        int r1 = r0 + 8;
#pragma unroll
        for (int nf = 0; nf < 4; ++nf) {
            int c = wn * 32 + nf * 8 + tig * 2;
            float bx = 0.f, by = 0.f;
            if (!isQ) {
                float2 b = *(const float2*)(be1 + c);
                bx = b.x; by = b.y;
            }
            if (r0 < M)
                *(float2*)(C + (size_t)r0 * H + c) =
                    make_float2(acc[mf][nf][0] + bx, acc[mf][nf][1] + by);
            if (r1 < M)
                *(float2*)(C + (size_t)r1 * H + c) =
                    make_float2(acc[mf][nf][2] + bx, acc[mf][nf][3] + by);
        }
    }
}

// ---------------- launch 3: persistent edge GEMM ----------------
// grid-stride over 64-edge tiles; W resident in smem; A prefetched into regs
__global__ void __launch_bounds__(256, 2)
edge_gemm(const float* __restrict__ EA, const char* __restrict__ wh, const char* __restrict__ wl,
          const int* __restrict__ rowi, const int* __restrict__ coli,
          const float* __restrict__ P, const float* __restrict__ Q,
          float* __restrict__ Hsum, int E, int nTiles) {
    extern __shared__ char sm[];
    uint32_t sb = smem_u32(sm);
    int tid = threadIdx.x, lane = tid & 31, wid = tid >> 5;
    int wm = wid & 1, wn = wid >> 1;
    int* rid = (int*)(sm + SM_RID);
    int* cid = (int*)(sm + SM_CID);
    int gid = lane >> 2, tig = lane & 3;
    int odd = tig & 1;

    copy_W(wh, wl, sm, tid);                 // once per CTA

    // prologue: prefetch first tile
    int t = blockIdx.x;
    float4 av[8];
    int pr = 0, pc = 0;
    if (t < nTiles) {
        fetch_A(EA, t * BM, E, av, tid);
        if (tid < 64) {
            int e = t * BM + tid;
            pr = (e < E) ? rowi[e] : 0;
            pc = (e < E) ? coli[e] : 0;
        }
    }

    for (; t < nTiles; t += gridDim.x) {
        int ge = t * BM;
        int tn = t + gridDim.x;
        // convert prefetched A -> smem; publish ids
        store_A(av, sm, tid);
        if (tid < 64) { rid[tid] = pr; cid[tid] = pc; }
        __syncthreads();

        float acc[2][4][4];
#pragma unroll
        for (int a = 0; a < 2; ++a)
#pragma unroll
            for (int b = 0; b < 4; ++b)
#pragma unroll
                for (int c = 0; c < 4; ++c) acc[a][b][c] = 0.f;
        gemm_hmma(sb, wm, wn, lane, acc);

        // prefetch next tile (overlaps epilogue reds)
        if (tn < nTiles) {
            fetch_A(EA, tn * BM, E, av, tid);
            if (tid < 64) {
                int e = tn * BM + tid;
                pr = (e < E) ? rowi[e] : 0;
                pc = (e < E) ? coli[e] : 0;
            }
        }

        // epilogue: shfl-pair into float4 rows; gather P/Q; relu; red.v4
#pragma unroll
        for (int mf = 0; mf < 2; ++mf) {
            int rl = wm * 32 + mf * 16 + gid + (odd << 3);
            int e = ge + rl;
            int r = rid[rl], c = cid[rl];
            bool ok = (e < E);
#pragma unroll
            for (int nf = 0; nf < 4; ++nf) {
                float sA = odd ? acc[mf][nf][0] : acc[mf][nf][2];
                float sB = odd ? acc[mf][nf][1] : acc[mf][nf][3];
                float rA = __shfl_xor_sync(0xffffffffu, sA, 1);
                float rB = __shfl_xor_sync(0xffffffffu, sB, 1);
                float4 v;
                if (odd) v = make_float4(rA, rB, acc[mf][nf][2], acc[mf][nf][3]);
                else     v = make_float4(acc[mf][nf][0], acc[mf][nf][1], rA, rB);
                int cb = wn * 32 + nf * 8 + (tig & 2) * 2;
                if (ok) {
                    float4 pv = *(const float4*)(P + (size_t)r * H + cb);
                    float4 qv = *(const float4*)(Q + (size_t)c * H + cb);
                    v.x = fmaxf(v.x + pv.x + qv.x, 0.f);
                    v.y = fmaxf(v.y + pv.y + qv.y, 0.f);
                    v.z = fmaxf(v.z + pv.z + qv.z, 0.f);
                    v.w = fmaxf(v.w + pv.w + qv.w, 0.f);
                    red_add_v4(Hsum + (size_t)c * H + cb, v);
                }
            }
        }
        __syncthreads();   // smem A/ids free for next iteration
    }
}

// ---------------- launches 4-6: node GEMMs ----------------
template<bool DUAL, bool RELU, int BIAS_MODE>
__global__ void __launch_bounds__(256, 2)
node_gemm(const float* __restrict__ A1, const char* __restrict__ w1h, const char* __restrict__ w1l,
          const float* __restrict__ A2, const char* __restrict__ w2h, const char* __restrict__ w2l,
          const float* __restrict__ bias, const int* __restrict__ cnt,
          float* __restrict__ C, int M) {
    extern __shared__ char sm[];
    uint32_t sb = smem_u32(sm);
    int tid = threadIdx.x, lane = tid & 31, wid = tid >> 5;
    int wm = wid & 1, wn = wid >> 1;
    int gm = blockIdx.x * BM;

    float acc[2][4][4];
#pragma unroll
    for (int a = 0; a < 2; ++a)
#pragma unroll
        for (int b = 0; b < 4; ++b)
#pragma unroll
            for (int c = 0; c < 4; ++c) acc[a][b][c] = 0.f;

    load_convert_A(A1, gm, M, sm, tid);
    copy_W(w1h, w1l, sm, tid);
    __syncthreads();
    gemm_hmma(sb, wm, wn, lane, acc);
    if (DUAL) {
        __syncthreads();
        load_convert_A(A2, gm, M, sm, tid);
        copy_W(w2h, w2l, sm, tid);
        __syncthreads();
        gemm_hmma(sb, wm, wn, lane, acc);
    }

    int gid = lane >> 2, tig = lane & 3;
#pragma unroll
    for (int mf = 0; mf < 2; ++mf) {
        int r0 = gm + wm * 32 + mf * 16 + gid;
        int r1 = r0 + 8;
        float d0 = 0.f, d1 = 0.f;
        if (BIAS_MODE == 2) {
            if (r0 < M) d0 = (float)cnt[r0];
            if (r1 < M) d1 = (float)cnt[r1];
        }
#pragma unroll
        for (int nf = 0; nf < 4; ++nf) {
            int c = wn * 32 + nf * 8 + tig * 2;
            float bx = 0.f, by = 0.f;
            if (BIAS_MODE != 0) {
                float2 b = *(const float2*)(bias + c);
                bx = b.x; by = b.y;
            }
            if (r0 < M) {
                float vx = acc[mf][nf][0], vy = acc[mf][nf][1];
                if (BIAS_MODE == 1) { vx += bx; vy += by; }
                else if (BIAS_MODE == 2) { vx += d0 * bx; vy += d0 * by; }
                if (RELU) { vx = fmaxf(vx, 0.f); vy = fmaxf(vy, 0.f); }
                *(float2*)(C + (size_t)r0 * H + c) = make_float2(vx, vy);
            }
            if (r1 < M) {
                float vx = acc[mf][nf][2], vy = acc[mf][nf][3];
                if (BIAS_MODE == 1) { vx += bx; vy += by; }
                else if (BIAS_MODE == 2) { vx += d1 * bx; vy += d1 * by; }
                if (RELU) { vx = fmaxf(vx, 0.f); vy = fmaxf(vy, 0.f); }
                *(float2*)(C + (size_t)r1 * H + c) = make_float2(vx, vy);
            }
        }
    }
}

// ---------------- host ----------------
extern "C" void kernel_launch(void* const* d_in, const int* in_sizes, int n_in,
                              void* d_out, int out_size) {
    const float* x   = (const float*)d_in[0];
    const void*  ei  = d_in[1];
    const float* ea  = (const float*)d_in[2];
    const float* We1 = (const float*)d_in[3];
    const float* be1 = (const float*)d_in[4];
    const float* We2 = (const float*)d_in[5];
    const float* be2 = (const float*)d_in[6];
    const float* Wn1 = (const float*)d_in[7];
    const float* bn1 = (const float*)d_in[8];
    const float* Wn2 = (const float*)d_in[9];
    const float* bn2 = (const float*)d_in[10];
    float* out = (float*)d_out;

    int N = in_sizes[0] / H;
    int E = in_sizes[1] / 2;

    void *pP, *pQ, *pHs, *pAgg, *pT, *pCnt, *pRow, *pCol, *pWimg;
    cudaGetSymbolAddress(&pP, g_P);
    cudaGetSymbolAddress(&pQ, g_Q);
    cudaGetSymbolAddress(&pHs, g_Hsum);
    cudaGetSymbolAddress(&pAgg, g_agg);
    cudaGetSymbolAddress(&pT, g_Tbuf);
    cudaGetSymbolAddress(&pCnt, g_cnt);
    cudaGetSymbolAddress(&pRow, g_row);
    cudaGetSymbolAddress(&pCol, g_col);
    cudaGetSymbolAddress(&pWimg, g_Wimg);
    float* P   = (float*)pP;
    float* Q   = (float*)pQ;
    float* Hs  = (float*)pHs;
    float* agg = (float*)pAgg;
    float* T   = (float*)pT;
    int*   cnt = (int*)pCnt;
    int*   ro  = (int*)pRow;
    int*   co  = (int*)pCol;
    const char* W = (const char*)pWimg;
    auto wH = [&](int t) { return W + (size_t)t * 32768; };
    auto wL = [&](int t) { return W + (size_t)(7 + t) * 32768; };

    cudaFuncSetAttribute(node_pq, cudaFuncAttributeMaxDynamicSharedMemorySize, SMEM_NODE);
    cudaFuncSetAttribute(edge_gemm, cudaFuncAttributeMaxDynamicSharedMemorySize, SMEM_EDGE);
    cudaFuncSetAttribute(node_gemm<false, false, 1>, cudaFuncAttributeMaxDynamicSharedMemorySize, SMEM_NODE);
    cudaFuncSetAttribute(node_gemm<false, false, 2>, cudaFuncAttributeMaxDynamicSharedMemorySize, SMEM_NODE);
    cudaFuncSetAttribute(node_gemm<true,  true,  1>, cudaFuncAttributeMaxDynamicSharedMemorySize, SMEM_NODE);

    int nodeBlocks = (N + BM - 1) / BM;              // 782
    int nTiles = (E + BM - 1) / BM;                  // 12500
    int nh = N * H;
    int cBlocks = (E + 255) / 256;                   // 3125
    int persistCTAs = 148 * 2;

    // launch 0: zero Hsum + cnt
    prep_zero<<<(nh + 255) / 256, 256>>>(Hs, cnt, nh, N);
    // launch 1: idx convert (per-block dtype sniff) + weight images
    prep_idx_w<<<cBlocks + 112, 256>>>(ei, E, N, cBlocks, ro, co, cnt, We1, We2, Wn1, Wn2);
    // launch 2: P = x@We1a + be1  AND  Q = x@We1b   (gridDim.y=2)
    node_pq<<<dim3(nodeBlocks, 2), 256, SMEM_NODE>>>(x, wH(0), wL(0), wH(1), wL(1), be1, P, Q, N);
    // launch 3 (ncu capture slot): persistent edge GEMM + scatter
    edge_gemm<<<persistCTAs, 256, SMEM_EDGE>>>(ea, wH(2), wL(2), ro, co, P, Q, Hs, E, nTiles);
    // launch 4: agg = Hsum@We2 + deg*be2
    node_gemm<false, false, 2><<<nodeBlocks, 256, SMEM_NODE>>>(Hs, wH(3), wL(3), nullptr, nullptr, nullptr, be2, cnt, agg, N);
    // launch 5: T = relu(x@Wn1a + agg@Wn1b + bn1)
    node_gemm<true, true, 1><<<nodeBlocks, 256, SMEM_NODE>>>(x, wH(4), wL(4), agg, wH(5), wL(5), bn1, nullptr, T, N);
    // launch 6: out = T@Wn2 + bn2
    node_gemm<false, false, 1><<<nodeBlocks, 256, SMEM_NODE>>>(T, wH(6), wL(6), nullptr, nullptr, nullptr, bn2, nullptr, out, N);
}